// round 1
// baseline (speedup 1.0000x reference)
#include <cuda_runtime.h>
#include <math.h>

#define T_TOKENS 8192
#define HID      1024
#define NE       64
#define TOPK     8
#define INTER    512
#define TK       (T_TOKENS * TOPK)   // 65536 (token, expert) pairs

// ----------------------------------------------------------------------------
// Scratch (device globals — no allocations allowed)
// ----------------------------------------------------------------------------
__device__ float g_merged[(size_t)TK * 1024];   // gate_up output [TK, 2*INTER]
__device__ float g_act[(size_t)TK * 512];       // silu(gate)*up  [TK, INTER]
__device__ float g_eout[(size_t)TK * 1024];     // down output    [TK, HID]
__device__ int   g_indices[TK];                 // expert id per (t,k)
__device__ float g_rweight[TK];                 // routing weight per (t,k)
__device__ int   g_row_token[TK];               // slot -> token
__device__ int   g_slot_of[TK];                 // (t,k) -> slot
__device__ int   g_counts[NE];
__device__ int   g_fill[NE];
__device__ int   g_offsets[NE + 1];
__device__ int   g_tile_off[NE + 1];
__device__ int   g_total_tiles;

// ----------------------------------------------------------------------------
// Init: zero counters (output is fully overwritten by combine)
// ----------------------------------------------------------------------------
__global__ void init_kernel() {
    int i = threadIdx.x;
    if (i < NE) { g_counts[i] = 0; g_fill[i] = 0; }
}

// ----------------------------------------------------------------------------
// Router: logits = x @ rw, then top-8 + softmax-over-top8 (== softmax, topk,
// renormalize — softmax is monotone so topk(probs) == topk(logits) and the
// renormalized weights are exp(l_i - m)/sum over the selected 8).
// Block handles 16 tokens with 256 threads; rw tile staged in SMEM.
// ----------------------------------------------------------------------------
__global__ void __launch_bounds__(256) router_kernel(const float* __restrict__ x,
                                                     const float* __restrict__ rw) {
    __shared__ float Xs[16][128];
    __shared__ float RWs[128][64];
    __shared__ float Ls[16][64];

    int tid = threadIdx.x;
    int t0  = blockIdx.x * 16;
    int e   = tid & 63;        // expert this thread accumulates
    int tg  = tid >> 6;        // token group 0..3 (4 tokens each)

    float acc0 = 0.f, acc1 = 0.f, acc2 = 0.f, acc3 = 0.f;

    for (int h0 = 0; h0 < HID; h0 += 128) {
        // stage X tile: 16 x 128 floats = 512 float4
        #pragma unroll
        for (int r = 0; r < 2; r++) {
            int f = tid + 256 * r;
            int tok = f >> 5, c4 = f & 31;
            *(float4*)&Xs[tok][c4 * 4] =
                *(const float4*)&x[(size_t)(t0 + tok) * HID + h0 + c4 * 4];
        }
        // stage RW tile: 128 x 64 floats = 2048 float4
        #pragma unroll
        for (int r = 0; r < 8; r++) {
            int f = tid + 256 * r;
            int hh = f >> 4, e4 = f & 15;
            *(float4*)&RWs[hh][e4 * 4] =
                *(const float4*)&rw[(size_t)(h0 + hh) * NE + e4 * 4];
        }
        __syncthreads();
        #pragma unroll 4
        for (int hh = 0; hh < 128; hh++) {
            float w = RWs[hh][e];
            acc0 += Xs[tg * 4 + 0][hh] * w;
            acc1 += Xs[tg * 4 + 1][hh] * w;
            acc2 += Xs[tg * 4 + 2][hh] * w;
            acc3 += Xs[tg * 4 + 3][hh] * w;
        }
        __syncthreads();
    }
    Ls[tg * 4 + 0][e] = acc0;
    Ls[tg * 4 + 1][e] = acc1;
    Ls[tg * 4 + 2][e] = acc2;
    Ls[tg * 4 + 3][e] = acc3;
    __syncthreads();

    if (tid < 16) {
        int t = tid;
        int   idx[TOPK];
        float val[TOPK];
        #pragma unroll
        for (int k = 0; k < TOPK; k++) {
            float best = -1e30f; int bi = 0;
            for (int ee = 0; ee < NE; ee++) {
                float v = Ls[t][ee];
                if (v > best) { best = v; bi = ee; }   // first max wins (stable)
            }
            idx[k] = bi; val[k] = best;
            Ls[t][bi] = -1e30f;
        }
        float m = val[0], s = 0.f, w[TOPK];
        #pragma unroll
        for (int k = 0; k < TOPK; k++) { w[k] = expf(val[k] - m); s += w[k]; }
        float inv = 1.f / s;
        int base = (t0 + t) * TOPK;
        #pragma unroll
        for (int k = 0; k < TOPK; k++) {
            g_indices[base + k] = idx[k];
            g_rweight[base + k] = w[k] * inv;
            atomicAdd(&g_counts[idx[k]], 1);
        }
    }
}

// ----------------------------------------------------------------------------
// Scan: exclusive offsets + per-expert 128-row tile map
// ----------------------------------------------------------------------------
__global__ void scan_kernel() {
    int off = 0, toff = 0;
    g_offsets[0] = 0; g_tile_off[0] = 0;
    for (int e = 0; e < NE; e++) {
        off  += g_counts[e];                g_offsets[e + 1]  = off;
        toff += (g_counts[e] + 127) >> 7;   g_tile_off[e + 1] = toff;
    }
    g_total_tiles = toff;
}

// ----------------------------------------------------------------------------
// Scatter: assign each (t,k) a slot inside its expert's group. Slot order is
// nondeterministic (atomics) but every derived row depends only on (token,
// expert), and the combine reads slots in fixed k-order, so the final output
// is bit-deterministic.
// ----------------------------------------------------------------------------
__global__ void scatter_kernel() {
    int i = blockIdx.x * blockDim.x + threadIdx.x;
    if (i >= TK) return;
    int e    = g_indices[i];
    int pos  = atomicAdd(&g_fill[e], 1);
    int slot = g_offsets[e] + pos;
    g_row_token[slot] = i >> 3;   // token id
    g_slot_of[i]      = slot;
}

// ----------------------------------------------------------------------------
// Grouped GEMM: 128x128x8 fp32 SMEM tiles, 256 threads, 8x8 micro-tile.
//   mode 0: A = hidden (rows gathered via g_row_token), W = gate_up[e]
//           (K=1024, lda=1024), C = g_merged
//   mode 1: A = g_act (direct rows, K=512, lda=512), W = down[e], C = g_eout
// N = 1024, ldc = 1024 in both cases.
// ----------------------------------------------------------------------------
__global__ void __launch_bounds__(256) grouped_gemm_kernel(
    const float* __restrict__ Aext, const float* __restrict__ W, int Kdim,
    int mode) {
    int bm = blockIdx.x;
    if (bm >= g_total_tiles) return;
    int e = 0;
    while (e < NE - 1 && g_tile_off[e + 1] <= bm) e++;
    int row_start  = g_offsets[e] + (bm - g_tile_off[e]) * 128;
    int rows_valid = g_offsets[e + 1] - row_start;
    if (rows_valid > 128) rows_valid = 128;
    int n0 = blockIdx.y * 128;

    const float* A = (mode == 0) ? Aext : g_act;
    float*       C = (mode == 0) ? g_merged : g_eout;
    int lda        = Kdim;          // 1024 for mode 0 (HID), 512 for mode 1
    const float* We = W + (size_t)e * Kdim * 1024;

    __shared__ float As[8][128];
    __shared__ float Bs[8][128];

    int tid = threadIdx.x;
    int tx  = tid & 15, ty = tid >> 4;

    int  arow   = tid >> 1;
    int  ak     = (tid & 1) * 4;
    bool avalid = arow < rows_valid;
    const float* aptr = A;
    if (avalid) {
        int r   = row_start + arow;
        int src = (mode == 0) ? g_row_token[r] : r;
        aptr = A + (size_t)src * lda;
    }
    int brow = tid >> 5;
    int bcol = (tid & 31) * 4;

    float acc[8][8];
    #pragma unroll
    for (int i = 0; i < 8; i++)
        #pragma unroll
        for (int j = 0; j < 8; j++) acc[i][j] = 0.f;

    for (int k0 = 0; k0 < Kdim; k0 += 8) {
        float4 a4 = make_float4(0.f, 0.f, 0.f, 0.f);
        if (avalid) a4 = *(const float4*)&aptr[k0 + ak];
        float4 b4 = *(const float4*)&We[(size_t)(k0 + brow) * 1024 + n0 + bcol];
        As[ak + 0][arow] = a4.x; As[ak + 1][arow] = a4.y;
        As[ak + 2][arow] = a4.z; As[ak + 3][arow] = a4.w;
        *(float4*)&Bs[brow][bcol] = b4;
        __syncthreads();
        #pragma unroll
        for (int kk = 0; kk < 8; kk++) {
            float af[8], bf[8];
            #pragma unroll
            for (int i = 0; i < 8; i++) af[i] = As[kk][ty * 8 + i];
            #pragma unroll
            for (int j = 0; j < 8; j++) bf[j] = Bs[kk][tx * 8 + j];
            #pragma unroll
            for (int i = 0; i < 8; i++)
                #pragma unroll
                for (int j = 0; j < 8; j++) acc[i][j] += af[i] * bf[j];
        }
        __syncthreads();
    }
    #pragma unroll
    for (int i = 0; i < 8; i++) {
        int rl = ty * 8 + i;
        if (rl < rows_valid) {
            size_t off = (size_t)(row_start + rl) * 1024 + n0 + tx * 8;
            *(float4*)&C[off]     = make_float4(acc[i][0], acc[i][1], acc[i][2], acc[i][3]);
            *(float4*)&C[off + 4] = make_float4(acc[i][4], acc[i][5], acc[i][6], acc[i][7]);
        }
    }
}

// ----------------------------------------------------------------------------
// SiLU gating: act = silu(merged[:, :512]) * merged[:, 512:]
// ----------------------------------------------------------------------------
__global__ void silu_kernel() {
    int i = blockIdx.x * blockDim.x + threadIdx.x;  // float4 id over [TK][128]
    if (i >= TK * 128) return;
    int row = i >> 7, c4 = i & 127;
    const float4 g = *(const float4*)&g_merged[(size_t)row * 1024 + c4 * 4];
    const float4 u = *(const float4*)&g_merged[(size_t)row * 1024 + 512 + c4 * 4];
    float4 o;
    o.x = g.x / (1.f + expf(-g.x)) * u.x;
    o.y = g.y / (1.f + expf(-g.y)) * u.y;
    o.z = g.z / (1.f + expf(-g.z)) * u.z;
    o.w = g.w / (1.f + expf(-g.w)) * u.w;
    *(float4*)&g_act[(size_t)row * 512 + c4 * 4] = o;
}

// ----------------------------------------------------------------------------
// Combine: out[t] = sum_k w[t,k] * eout[slot_of[t,k]]  (fixed k order)
// ----------------------------------------------------------------------------
__global__ void __launch_bounds__(256) combine_kernel(float* __restrict__ out) {
    int t  = blockIdx.x;
    int c4 = threadIdx.x;                 // 256 float4 per row of 1024
    float4 acc = make_float4(0.f, 0.f, 0.f, 0.f);
    #pragma unroll
    for (int k = 0; k < TOPK; k++) {
        int   slot = g_slot_of[t * TOPK + k];
        float w    = g_rweight[t * TOPK + k];
        float4 v = *(const float4*)&g_eout[(size_t)slot * 1024 + c4 * 4];
        acc.x += w * v.x; acc.y += w * v.y; acc.z += w * v.z; acc.w += w * v.w;
    }
    *(float4*)&out[(size_t)t * 1024 + c4 * 4] = acc;
}

// ----------------------------------------------------------------------------
// Launch
// ----------------------------------------------------------------------------
extern "C" void kernel_launch(void* const* d_in, const int* in_sizes, int n_in,
                              void* d_out, int out_size) {
    const float* x   = (const float*)d_in[0];   // [8192, 1024]
    const float* rw  = (const float*)d_in[1];   // [1024, 64]
    const float* wgu = (const float*)d_in[2];   // [64, 1024, 1024]
    const float* wd  = (const float*)d_in[3];   // [64, 512, 1024]
    float* out = (float*)d_out;                 // [8192, 1024]

    init_kernel<<<1, 64>>>();
    router_kernel<<<T_TOKENS / 16, 256>>>(x, rw);
    scan_kernel<<<1, 1>>>();
    scatter_kernel<<<TK / 256, 256>>>();

    dim3 ggrid(TK / 128 + NE, 8);               // 576 m-tiles upper bound, 8 n-tiles
    grouped_gemm_kernel<<<ggrid, 256>>>(x, wgu, 1024, 0);
    silu_kernel<<<(TK * 128) / 256, 256>>>();
    grouped_gemm_kernel<<<ggrid, 256>>>(nullptr, wd, 512, 1);
    combine_kernel<<<T_TOKENS, 256>>>(out);
}

// round 11
// speedup vs baseline: 2.2383x; 2.2383x over previous
#include <cuda_runtime.h>
#include <cuda_bf16.h>
#include <math.h>

#define T_TOKENS 8192
#define HID      1024
#define NE       64
#define TOPK     8
#define INTER    512
#define TK       (T_TOKENS * TOPK)     // 65536 (token, expert) pairs
#define TILE_M   64
#define MAX_TILES (TK / TILE_M + NE)   // 1088

typedef __nv_bfloat16 bf16;

// ----------------------------------------------------------------------------
// Scratch: ~1 MiB of device globals only (no big buffers — everything large
// lives in SMEM inside the fused kernel; the harness memory guard trips on
// lazily-committed statics, so they must stay tiny).
// ----------------------------------------------------------------------------
__device__ int   g_indices[TK];
__device__ float g_rweight[TK];
__device__ int   g_row_token[TK];      // slot -> token
__device__ float g_slot_w[TK];         // slot -> routing weight
__device__ int   g_counts[NE];
__device__ int   g_fill[NE];
__device__ int   g_offsets[NE + 1];
__device__ int   g_tile_off[NE + 1];   // 64-row tiles
__device__ int   g_total_tiles;

// ----------------------------------------------------------------------------
__global__ void init_kernel() {
    int i = threadIdx.x;
    if (i < NE) { g_counts[i] = 0; g_fill[i] = 0; }
}

// zero the output (harness poisons it; fused GEMM2 accumulates atomically)
__global__ void zero_out_kernel(float* __restrict__ out) {
    size_t i = (size_t)blockIdx.x * blockDim.x + threadIdx.x;
    *(float4*)&out[i * 4] = make_float4(0.f, 0.f, 0.f, 0.f);
}

// ----------------------------------------------------------------------------
// pack two fp32 into one u32 bf16 hi-pair and one u32 bf16 residual-pair
// (.x = low 16 bits = first element => matches k-major [k][k+1] pair order)
// ----------------------------------------------------------------------------
__device__ __forceinline__ void split_pack(float a, float b,
                                           unsigned& hi, unsigned& lo) {
    __nv_bfloat162 h = __float22bfloat162_rn(make_float2(a, b));
    float2 hf = __bfloat1622float2(h);
    __nv_bfloat162 l = __float22bfloat162_rn(make_float2(a - hf.x, b - hf.y));
    hi = *(unsigned*)&h;
    lo = *(unsigned*)&l;
}

// ----------------------------------------------------------------------------
// Router (fp32, exact): logits -> top8 -> softmax over top8
// ----------------------------------------------------------------------------
__global__ void __launch_bounds__(256) router_kernel(const float* __restrict__ x,
                                                     const float* __restrict__ rw) {
    __shared__ float Xs[16][128];
    __shared__ float RWs[128][64];
    __shared__ float Ls[16][64];

    int tid = threadIdx.x;
    int t0  = blockIdx.x * 16;
    int e   = tid & 63;
    int tg  = tid >> 6;

    float acc0 = 0.f, acc1 = 0.f, acc2 = 0.f, acc3 = 0.f;

    for (int h0 = 0; h0 < HID; h0 += 128) {
        #pragma unroll
        for (int r = 0; r < 2; r++) {
            int f = tid + 256 * r;
            int tok = f >> 5, c4 = f & 31;
            *(float4*)&Xs[tok][c4 * 4] =
                *(const float4*)&x[(size_t)(t0 + tok) * HID + h0 + c4 * 4];
        }
        #pragma unroll
        for (int r = 0; r < 8; r++) {
            int f = tid + 256 * r;
            int hh = f >> 4, e4 = f & 15;
            *(float4*)&RWs[hh][e4 * 4] =
                *(const float4*)&rw[(size_t)(h0 + hh) * NE + e4 * 4];
        }
        __syncthreads();
        #pragma unroll 4
        for (int hh = 0; hh < 128; hh++) {
            float w = RWs[hh][e];
            acc0 += Xs[tg * 4 + 0][hh] * w;
            acc1 += Xs[tg * 4 + 1][hh] * w;
            acc2 += Xs[tg * 4 + 2][hh] * w;
            acc3 += Xs[tg * 4 + 3][hh] * w;
        }
        __syncthreads();
    }
    Ls[tg * 4 + 0][e] = acc0;
    Ls[tg * 4 + 1][e] = acc1;
    Ls[tg * 4 + 2][e] = acc2;
    Ls[tg * 4 + 3][e] = acc3;
    __syncthreads();

    if (tid < 16) {
        int t = tid;
        int   idx[TOPK];
        float val[TOPK];
        #pragma unroll
        for (int k = 0; k < TOPK; k++) {
            float best = -1e30f; int bi = 0;
            for (int ee = 0; ee < NE; ee++) {
                float v = Ls[t][ee];
                if (v > best) { best = v; bi = ee; }
            }
            idx[k] = bi; val[k] = best;
            Ls[t][bi] = -1e30f;
        }
        float m = val[0], s = 0.f, w[TOPK];
        #pragma unroll
        for (int k = 0; k < TOPK; k++) { w[k] = expf(val[k] - m); s += w[k]; }
        float inv = 1.f / s;
        int base = (t0 + t) * TOPK;
        #pragma unroll
        for (int k = 0; k < TOPK; k++) {
            g_indices[base + k] = idx[k];
            g_rweight[base + k] = w[k] * inv;
            atomicAdd(&g_counts[idx[k]], 1);
        }
    }
}

// ----------------------------------------------------------------------------
__global__ void scan_kernel() {
    int off = 0, toff = 0;
    g_offsets[0] = 0; g_tile_off[0] = 0;
    for (int e = 0; e < NE; e++) {
        off  += g_counts[e];               g_offsets[e + 1]  = off;
        toff += (g_counts[e] + 63) >> 6;   g_tile_off[e + 1] = toff;
    }
    g_total_tiles = toff;
}

__global__ void scatter_kernel() {
    int i = blockIdx.x * blockDim.x + threadIdx.x;
    if (i >= TK) return;
    int e    = g_indices[i];
    int pos  = atomicAdd(&g_fill[e], 1);
    int slot = g_offsets[e] + pos;
    g_row_token[slot] = i >> 3;
    g_slot_w[slot]    = g_rweight[i];
}

// ----------------------------------------------------------------------------
// Fused expert kernel, one 64-row slot tile per block, 256 threads (8 warps,
// warp grid 2(m)x4(n), warp tile 32x32). 3-term bf16-split tensor-core MMA
// (C += Ahi*Bhi + Ahi*Blo + Alo*Bhi) for fp32-class accuracy.
//
// Phase A (x @ Wgu + SiLU): for 4 column chunks, compute gate cols
// [nc*128,+128) and up cols +512 simultaneously over K=1024, then
// act = silu(gate)*up -> SMEM as bf16 hi/lo (u32 k-pairs, row stride 260).
// Phase B (act @ Wd + combine): for 8 column chunks over K=512, A-frags read
// straight from act SMEM; epilogue does out[token] += w_slot * val via
// atomicAdd (RED.global).
//
// All global operands are fp32, split to bf16 hi/lo on the fly (4B/elem
// either way — no extra DRAM traffic, no conversion pre-pass, no big statics).
// Register-level prefetch of the next k-chunk overlaps LDG with MMA.
// SMEM u32 layout, all fragment access patterns bank-conflict-free.
// ----------------------------------------------------------------------------
__device__ __forceinline__ void mma_bf16(float* c, const unsigned* a, const unsigned* b) {
    asm volatile(
        "mma.sync.aligned.m16n8k16.row.col.f32.bf16.bf16.f32 "
        "{%0,%1,%2,%3}, {%4,%5,%6,%7}, {%8,%9}, {%0,%1,%2,%3};"
        : "+f"(c[0]), "+f"(c[1]), "+f"(c[2]), "+f"(c[3])
        : "r"(a[0]), "r"(a[1]), "r"(a[2]), "r"(a[3]), "r"(b[0]), "r"(b[1]));
}

// dynamic SMEM partition (u32 units)
#define OFF_AS_HI  0               // 64 rows x 20
#define OFF_AS_LO  1280
#define OFF_BS_HI  2560            // 256 n-rows x 20 (gate 0..127, up 128..255)
#define OFF_BS_LO  7680
#define OFF_ACT_HI 12800           // 64 rows x 260 (256 k-pairs + 4 pad)
#define OFF_ACT_LO 29440
#define SMEM_U32   46080
#define SMEM_BYTES (SMEM_U32 * 4)  // 184320

__global__ void __launch_bounds__(256) fused_moe_kernel(
    const float* __restrict__ x, const float* __restrict__ wgu,
    const float* __restrict__ wd, float* __restrict__ out) {

    extern __shared__ unsigned sm[];
    unsigned* As_hi  = sm + OFF_AS_HI;
    unsigned* As_lo  = sm + OFF_AS_LO;
    unsigned* Bs_hi  = sm + OFF_BS_HI;
    unsigned* Bs_lo  = sm + OFF_BS_LO;
    unsigned* act_hi = sm + OFF_ACT_HI;
    unsigned* act_lo = sm + OFF_ACT_LO;

    int bm = blockIdx.x;
    if (bm >= g_total_tiles) return;
    int e = 0;
    while (e < NE - 1 && g_tile_off[e + 1] <= bm) e++;
    int row_start  = g_offsets[e] + (bm - g_tile_off[e]) * TILE_M;
    int rows_valid = g_offsets[e + 1] - row_start;
    if (rows_valid > TILE_M) rows_valid = TILE_M;

    int tid  = threadIdx.x;
    int lane = tid & 31;
    int wid  = tid >> 5;
    int wm   = (wid >> 2) * 32;   // warp m offset (0 or 32)
    int wn   = (wid & 3) * 32;    // warp n offset (0..96)
    int gq   = lane >> 2;
    int tq   = lane & 3;

    // A loader: row = tid>>2 (0..63), 8-k granule = tid&3
    int arow = tid >> 2, g4 = tid & 3;
    int ar   = arow < rows_valid ? arow : 0;
    const float* afp = x + (size_t)g_row_token[row_start + ar] * HID + g4 * 8;
    int asoff = arow * 20 + g4 * 4;

    // B loader: one n-col (bn), one 16-k half (bkh) per thread
    int bn = tid & 127, bkh = tid >> 7;
    int bs_g = bn * 20 + bkh * 8;
    int bs_u = (128 + bn) * 20 + bkh * 8;

    // ======================= Phase A: gate/up + SiLU =======================
    const float* wgu_e = wgu + (size_t)e * HID * 1024;
    for (int nc = 0; nc < 4; nc++) {
        int gn0 = nc * 128;
        float accg[2][4][4], accu[2][4][4];
        #pragma unroll
        for (int mi = 0; mi < 2; mi++)
            #pragma unroll
            for (int ni = 0; ni < 4; ni++)
                #pragma unroll
                for (int q = 0; q < 4; q++) { accg[mi][ni][q] = 0.f; accu[mi][ni][q] = 0.f; }

        // prefetch chunk 0
        float4 a0v = *(const float4*)(afp);
        float4 a1v = *(const float4*)(afp + 4);
        float bg[16], bu[16];
        {
            const float* bp = wgu_e + (size_t)(bkh * 16) * 1024 + gn0 + bn;
            #pragma unroll
            for (int kk = 0; kk < 16; kk++) {
                bg[kk] = bp[(size_t)kk * 1024];
                bu[kk] = bp[(size_t)kk * 1024 + 512];
            }
        }

        for (int k0 = 0; k0 < HID; k0 += 32) {
            // stage prefetched chunk into SMEM (with fp32 -> bf16 hi/lo split)
            {
                uint4 ha, la;
                split_pack(a0v.x, a0v.y, ha.x, la.x);
                split_pack(a0v.z, a0v.w, ha.y, la.y);
                split_pack(a1v.x, a1v.y, ha.z, la.z);
                split_pack(a1v.z, a1v.w, ha.w, la.w);
                *(uint4*)&As_hi[asoff] = ha;
                *(uint4*)&As_lo[asoff] = la;
                #pragma unroll
                for (int kp = 0; kp < 8; kp++) {
                    unsigned h, l;
                    split_pack(bg[2 * kp], bg[2 * kp + 1], h, l);
                    Bs_hi[bs_g + kp] = h; Bs_lo[bs_g + kp] = l;
                    split_pack(bu[2 * kp], bu[2 * kp + 1], h, l);
                    Bs_hi[bs_u + kp] = h; Bs_lo[bs_u + kp] = l;
                }
            }
            __syncthreads();
            // prefetch next chunk (overlaps with MMA below)
            if (k0 + 32 < HID) {
                a0v = *(const float4*)(afp + k0 + 32);
                a1v = *(const float4*)(afp + k0 + 36);
                const float* bp = wgu_e + (size_t)(k0 + 32 + bkh * 16) * 1024 + gn0 + bn;
                #pragma unroll
                for (int kk = 0; kk < 16; kk++) {
                    bg[kk] = bp[(size_t)kk * 1024];
                    bu[kk] = bp[(size_t)kk * 1024 + 512];
                }
            }
            // MMA
            #pragma unroll
            for (int ks = 0; ks < 2; ks++) {
                unsigned Ah[2][4], Al[2][4];
                #pragma unroll
                for (int mi = 0; mi < 2; mi++) {
                    int ra = (wm + mi * 16 + gq) * 20 + ks * 8;
                    Ah[mi][0] = As_hi[ra + tq];       Ah[mi][1] = As_hi[ra + 160 + tq];
                    Ah[mi][2] = As_hi[ra + tq + 4];   Ah[mi][3] = As_hi[ra + 160 + tq + 4];
                    Al[mi][0] = As_lo[ra + tq];       Al[mi][1] = As_lo[ra + 160 + tq];
                    Al[mi][2] = As_lo[ra + tq + 4];   Al[mi][3] = As_lo[ra + 160 + tq + 4];
                }
                #pragma unroll
                for (int ni = 0; ni < 4; ni++) {
                    int rg = (wn + ni * 8 + gq) * 20 + ks * 8;
                    int ru = rg + 128 * 20;
                    unsigned Bgh[2] = { Bs_hi[rg + tq], Bs_hi[rg + tq + 4] };
                    unsigned Bgl[2] = { Bs_lo[rg + tq], Bs_lo[rg + tq + 4] };
                    unsigned Buh[2] = { Bs_hi[ru + tq], Bs_hi[ru + tq + 4] };
                    unsigned Bul[2] = { Bs_lo[ru + tq], Bs_lo[ru + tq + 4] };
                    #pragma unroll
                    for (int mi = 0; mi < 2; mi++) {
                        mma_bf16(accg[mi][ni], Ah[mi], Bgh);
                        mma_bf16(accg[mi][ni], Ah[mi], Bgl);
                        mma_bf16(accg[mi][ni], Al[mi], Bgh);
                        mma_bf16(accu[mi][ni], Ah[mi], Buh);
                        mma_bf16(accu[mi][ni], Ah[mi], Bul);
                        mma_bf16(accu[mi][ni], Al[mi], Buh);
                    }
                }
            }
            __syncthreads();
        }

        // SiLU epilogue -> act SMEM (each thread owns distinct (row, col pair))
        #pragma unroll
        for (int mi = 0; mi < 2; mi++) {
            int r0 = wm + mi * 16 + gq;
            int r1 = r0 + 8;
            #pragma unroll
            for (int ni = 0; ni < 4; ni++) {
                int cidx = nc * 64 + (wn >> 1) + ni * 4 + tq;
                float gA = accg[mi][ni][0], gB = accg[mi][ni][1];
                float a0 = gA / (1.f + expf(-gA)) * accu[mi][ni][0];
                float a1 = gB / (1.f + expf(-gB)) * accu[mi][ni][1];
                unsigned h, l;
                split_pack(a0, a1, h, l);
                act_hi[r0 * 260 + cidx] = h; act_lo[r0 * 260 + cidx] = l;
                gA = accg[mi][ni][2]; gB = accg[mi][ni][3];
                a0 = gA / (1.f + expf(-gA)) * accu[mi][ni][2];
                a1 = gB / (1.f + expf(-gB)) * accu[mi][ni][3];
                split_pack(a0, a1, h, l);
                act_hi[r1 * 260 + cidx] = h; act_lo[r1 * 260 + cidx] = l;
            }
        }
    }
    __syncthreads();   // act fully written before Phase B reads all rows

    // ======================= Phase B: down proj + combine ==================
    const float* wd_e = wd + (size_t)e * INTER * 1024;
    for (int nc2 = 0; nc2 < 8; nc2++) {
        int n0 = nc2 * 128;
        float acc[2][4][4];
        #pragma unroll
        for (int mi = 0; mi < 2; mi++)
            #pragma unroll
            for (int ni = 0; ni < 4; ni++)
                #pragma unroll
                for (int q = 0; q < 4; q++) acc[mi][ni][q] = 0.f;

        float bv[16];
        {
            const float* bp = wd_e + (size_t)(bkh * 16) * 1024 + n0 + bn;
            #pragma unroll
            for (int kk = 0; kk < 16; kk++) bv[kk] = bp[(size_t)kk * 1024];
        }

        for (int k0 = 0; k0 < INTER; k0 += 32) {
            #pragma unroll
            for (int kp = 0; kp < 8; kp++) {
                unsigned h, l;
                split_pack(bv[2 * kp], bv[2 * kp + 1], h, l);
                Bs_hi[bs_g + kp] = h; Bs_lo[bs_g + kp] = l;
            }
            __syncthreads();
            if (k0 + 32 < INTER) {
                const float* bp = wd_e + (size_t)(k0 + 32 + bkh * 16) * 1024 + n0 + bn;
                #pragma unroll
                for (int kk = 0; kk < 16; kk++) bv[kk] = bp[(size_t)kk * 1024];
            }
            #pragma unroll
            for (int ks = 0; ks < 2; ks++) {
                unsigned Ah[2][4], Al[2][4];
                #pragma unroll
                for (int mi = 0; mi < 2; mi++) {
                    int ab = (wm + mi * 16 + gq) * 260 + (k0 >> 1) + ks * 8;
                    Ah[mi][0] = act_hi[ab + tq];      Ah[mi][1] = act_hi[ab + 2080 + tq];
                    Ah[mi][2] = act_hi[ab + tq + 4];  Ah[mi][3] = act_hi[ab + 2080 + tq + 4];
                    Al[mi][0] = act_lo[ab + tq];      Al[mi][1] = act_lo[ab + 2080 + tq];
                    Al[mi][2] = act_lo[ab + tq + 4];  Al[mi][3] = act_lo[ab + 2080 + tq + 4];
                }
                #pragma unroll
                for (int ni = 0; ni < 4; ni++) {
                    int rb = (wn + ni * 8 + gq) * 20 + ks * 8;
                    unsigned Bh[2] = { Bs_hi[rb + tq], Bs_hi[rb + tq + 4] };
                    unsigned Bl[2] = { Bs_lo[rb + tq], Bs_lo[rb + tq + 4] };
                    #pragma unroll
                    for (int mi = 0; mi < 2; mi++) {
                        mma_bf16(acc[mi][ni], Ah[mi], Bh);
                        mma_bf16(acc[mi][ni], Ah[mi], Bl);
                        mma_bf16(acc[mi][ni], Al[mi], Bh);
                    }
                }
            }
            __syncthreads();
        }

        // fused combine: out[token] += w_slot * val
        #pragma unroll
        for (int mi = 0; mi < 2; mi++) {
            int r0 = wm + mi * 16 + gq, r1 = r0 + 8;
            bool v0 = r0 < rows_valid, v1 = r1 < rows_valid;
            int   t0v = 0, t1v = 0;
            float w0 = 0.f, w1 = 0.f;
            if (v0) { t0v = g_row_token[row_start + r0]; w0 = g_slot_w[row_start + r0]; }
            if (v1) { t1v = g_row_token[row_start + r1]; w1 = g_slot_w[row_start + r1]; }
            #pragma unroll
            for (int ni = 0; ni < 4; ni++) {
                int col = n0 + wn + ni * 8 + tq * 2;
                if (v0) {
                    float* o = &out[(size_t)t0v * 1024 + col];
                    atomicAdd(o,     w0 * acc[mi][ni][0]);
                    atomicAdd(o + 1, w0 * acc[mi][ni][1]);
                }
                if (v1) {
                    float* o = &out[(size_t)t1v * 1024 + col];
                    atomicAdd(o,     w1 * acc[mi][ni][2]);
                    atomicAdd(o + 1, w1 * acc[mi][ni][3]);
                }
            }
        }
    }
}

// ----------------------------------------------------------------------------
extern "C" void kernel_launch(void* const* d_in, const int* in_sizes, int n_in,
                              void* d_out, int out_size) {
    const float* x   = (const float*)d_in[0];   // [8192, 1024]
    const float* rw  = (const float*)d_in[1];   // [1024, 64]
    const float* wgu = (const float*)d_in[2];   // [64, 1024, 1024]
    const float* wd  = (const float*)d_in[3];   // [64, 512, 1024]
    float* out = (float*)d_out;                 // [8192, 1024]

    static bool attr_set = false;
    if (!attr_set) {
        cudaFuncSetAttribute(fused_moe_kernel,
                             cudaFuncAttributeMaxDynamicSharedMemorySize,
                             SMEM_BYTES);
        attr_set = true;
    }

    init_kernel<<<1, 64>>>();
    zero_out_kernel<<<(T_TOKENS * HID / 4) / 256, 256>>>(out);
    router_kernel<<<T_TOKENS / 16, 256>>>(x, rw);
    scan_kernel<<<1, 1>>>();
    scatter_kernel<<<TK / 256, 256>>>();
    fused_moe_kernel<<<MAX_TILES, 256, SMEM_BYTES>>>(x, wgu, wd, out);
}